// round 1
// baseline (speedup 1.0000x reference)
#include <cuda_runtime.h>

#define BATCH    256
#define IN_CAPS  1152
#define IN_DIM   8
#define NUM_CAPS 10
#define DIM_VEC  16
#define I_TILE   16
#define B_TILE   32
#define N_ITILES (IN_CAPS / I_TILE)   // 72
#define N_BTILES (BATCH / B_TILE)     // 8
#define NTHREADS (B_TILE * NUM_CAPS)  // 320
#define EPS 1e-7f

// Scratch (zero-initialized at module load; every launch leaves g_s zeroed again)
__device__ float g_s[BATCH * NUM_CAPS * DIM_VEC];
__device__ float g_v[BATCH * NUM_CAPS * DIM_VEC];
__device__ float g_blog[IN_CAPS * NUM_CAPS * BATCH];

// PASS 0: c = softmax(bias); s1 += c*u_hat
// PASS 1: agr = u_hat.v1; b1 = agr + 2*bias (store); c = softmax(b1); s2 += c*u_hat
// PASS 2: agr = u_hat.v2; b2 = agr + b1 + bias; c = softmax(b2); s3 += c*u_hat
template <int PASS>
__global__ __launch_bounds__(NTHREADS)
void pass_kernel(const float* __restrict__ x,     // [B,1152,8]
                 const float* __restrict__ W,     // [1152,10,16,8]
                 const float* __restrict__ bias)  // [1152,10]
{
    __shared__ float xs[B_TILE][I_TILE * IN_DIM];  // 16 KB
    __shared__ float sm[B_TILE][NUM_CAPS + 1];     // padded: conflict-free

    const int bb  = threadIdx.x;               // 0..31 (lane)
    const int c   = threadIdx.y;               // 0..9
    const int i0  = blockIdx.x * I_TILE;
    const int b0  = blockIdx.y * B_TILE;
    const int b   = b0 + bb;
    const int tid = threadIdx.y * B_TILE + threadIdx.x;

    // Cooperative stage of the x tile: per bb, 128 consecutive floats from global
    for (int t = tid; t < B_TILE * I_TILE * IN_DIM; t += NTHREADS) {
        int lb = t >> 7;        // which b in tile
        int j  = t & 127;       // 16 i * 8 e flattened (contiguous in global)
        xs[lb][j] = x[(b0 + lb) * (IN_CAPS * IN_DIM) + i0 * IN_DIM + j];
    }
    __syncthreads();

    // v[b,c,:] is invariant over i -> preload once per thread
    float vv[DIM_VEC];
    if (PASS > 0) {
        const float* vp = g_v + (b * NUM_CAPS + c) * DIM_VEC;
        #pragma unroll
        for (int d = 0; d < DIM_VEC; d++) vv[d] = vp[d];
    }

    float sacc[DIM_VEC];
    #pragma unroll
    for (int d = 0; d < DIM_VEC; d++) sacc[d] = 0.f;

    for (int ii = 0; ii < I_TILE; ii++) {
        const int i = i0 + ii;
        const float* wp = W + (i * NUM_CAPS + c) * (DIM_VEC * IN_DIM);  // warp-uniform
        float xv[IN_DIM];
        #pragma unroll
        for (int e = 0; e < IN_DIM; e++) xv[e] = xs[bb][ii * IN_DIM + e];

        // u_hat[c,:] for this (b,i): 128 FMA
        float uh[DIM_VEC];
        #pragma unroll
        for (int d = 0; d < DIM_VEC; d++) {
            float acc = 0.f;
            #pragma unroll
            for (int e = 0; e < IN_DIM; e++)
                acc = fmaf(wp[d * IN_DIM + e], xv[e], acc);
            uh[d] = acc;
        }

        const float bs = __ldg(&bias[i * NUM_CAPS + c]);  // warp-uniform
        float bnew;
        if (PASS == 0) {
            bnew = bs;
        } else {
            float agr = 0.f;
            #pragma unroll
            for (int d = 0; d < DIM_VEC; d++) agr = fmaf(uh[d], vv[d], agr);
            if (PASS == 1) {
                bnew = agr + 2.f * bs;
                g_blog[(i * NUM_CAPS + c) * BATCH + b] = bnew;   // coalesced over bb
            } else {
                bnew = agr + g_blog[(i * NUM_CAPS + c) * BATCH + b] + bs;
            }
        }

        // softmax over the 10 c's of this (b,i) via shared exchange
        sm[bb][c] = bnew;
        __syncthreads();
        float m = sm[bb][0];
        #pragma unroll
        for (int k = 1; k < NUM_CAPS; k++) m = fmaxf(m, sm[bb][k]);
        float den = 0.f;
        #pragma unroll
        for (int k = 0; k < NUM_CAPS; k++) den += __expf(sm[bb][k] - m);
        float coef = __expf(bnew - m) / den;
        __syncthreads();   // protect sm before next iteration's write

        #pragma unroll
        for (int d = 0; d < DIM_VEC; d++) sacc[d] = fmaf(coef, uh[d], sacc[d]);
    }

    // Block-local partial of s[b,c,:] over its 16 i's -> 72 atomic adds per address total
    float* sp = g_s + (b * NUM_CAPS + c) * DIM_VEC;
    #pragma unroll
    for (int d = 0; d < DIM_VEC; d++) atomicAdd(&sp[d], sacc[d]);
}

// squash s -> (v or out); re-zero s for the next pass / next launch (determinism)
template <bool FINAL>
__global__ void squash_kernel(float* __restrict__ out)
{
    int t = blockIdx.x * blockDim.x + threadIdx.x;   // (b,c) row
    if (t >= BATCH * NUM_CAPS) return;
    float* sp = g_s + t * DIM_VEC;
    float sv[DIM_VEC];
    float sq = 0.f;
    #pragma unroll
    for (int d = 0; d < DIM_VEC; d++) { sv[d] = sp[d]; sq = fmaf(sv[d], sv[d], sq); }
    float scale = sq / (1.f + sq) / sqrtf(sq + EPS);
    float* dst = FINAL ? (out + t * DIM_VEC) : (g_v + t * DIM_VEC);
    #pragma unroll
    for (int d = 0; d < DIM_VEC; d++) { dst[d] = scale * sv[d]; sp[d] = 0.f; }
}

extern "C" void kernel_launch(void* const* d_in, const int* in_sizes, int n_in,
                              void* d_out, int out_size)
{
    // Identify inputs by element count (robust to ordering)
    const float* x = nullptr; const float* W = nullptr; const float* bias = nullptr;
    for (int k = 0; k < n_in; k++) {
        if (in_sizes[k] == BATCH * IN_CAPS * IN_DIM)              x    = (const float*)d_in[k];
        else if (in_sizes[k] == IN_CAPS * NUM_CAPS * DIM_VEC * IN_DIM) W = (const float*)d_in[k];
        else if (in_sizes[k] == IN_CAPS * NUM_CAPS)               bias = (const float*)d_in[k];
    }
    float* out = (float*)d_out;

    dim3 blk(B_TILE, NUM_CAPS);
    dim3 grd(N_ITILES, N_BTILES);
    const int vgrid = (BATCH * NUM_CAPS + 255) / 256;

    pass_kernel<0><<<grd, blk>>>(x, W, bias);
    squash_kernel<false><<<vgrid, 256>>>(out);
    pass_kernel<1><<<grd, blk>>>(x, W, bias);
    squash_kernel<false><<<vgrid, 256>>>(out);
    pass_kernel<2><<<grd, blk>>>(x, W, bias);
    squash_kernel<true><<<vgrid, 256>>>(out);
}

// round 2
// speedup vs baseline: 1.5004x; 1.5004x over previous
#include <cuda_runtime.h>

#define BATCH    256
#define IN_CAPS  1152
#define IN_DIM   8
#define NUM_CAPS 10
#define DIM_VEC  16
#define I_TILE   16
#define B_TILE   32
#define N_ITILES (IN_CAPS / I_TILE)   // 72
#define N_BTILES (BATCH / B_TILE)     // 8
#define NTH      (B_TILE * NUM_CAPS)  // 320
#define EPS 1e-7f

// Shared memory carve-up (floats)
#define WS_F  (NUM_CAPS * I_TILE * IN_DIM * DIM_VEC)   // 20480 (80 KB)
#define XS_F  (I_TILE * IN_DIM * (B_TILE + 1))         // 4224  (16.5 KB)
#define SM_F  (2 * B_TILE * (NUM_CAPS + 1))            // 704
#define SMEM_BYTES ((WS_F + XS_F + 2 * SM_F) * 4)      // 104448 B

// Scratch: triple-buffered s (zero at load; final kernel re-zeros), b-logits
__device__ float g_sbuf[3][BATCH * NUM_CAPS * DIM_VEC];
__device__ float g_blog[IN_CAPS * NUM_CAPS * BATCH];

using ull = unsigned long long;
__device__ __forceinline__ ull pack2(float lo, float hi) {
    ull r; asm("mov.b64 %0,{%1,%2};" : "=l"(r) : "f"(lo), "f"(hi)); return r;
}
__device__ __forceinline__ void unpack2(ull v, float& lo, float& hi) {
    asm("mov.b64 {%0,%1},%2;" : "=f"(lo), "=f"(hi) : "l"(v));
}
__device__ __forceinline__ ull ffma2(ull a, ull b, ull c) {
    ull d; asm("fma.rn.f32x2 %0,%1,%2,%3;" : "=l"(d) : "l"(a), "l"(b), "l"(c)); return d;
}

// PASS 0: c = softmax(bias); s0 += c*u_hat
// PASS 1: v1 = squash(s0); b1 = u_hat.v1 + 2*bias (store); s1 += softmax(b1)*u_hat
// PASS 2: v2 = squash(s1); b2 = u_hat.v2 + b1 + bias;      s2 += softmax(b2)*u_hat
template <int PASS>
__global__ void __launch_bounds__(NTH, 2)
pass_kernel(const float* __restrict__ x,     // [B,1152,8]
            const float* __restrict__ W,     // [1152,10,16,8]
            const float* __restrict__ bias)  // [1152,10]
{
    extern __shared__ float sh[];
    float* ws  = sh;                 // [c][ii][e][d] : transposed W tile
    float* xs  = sh + WS_F;          // [j][B_TILE+1] : x tile, conflict-free
    float* smx = xs + XS_F;          // [2][32][11]   : bnew exchange (double buf)
    float* sme = smx + SM_F;         // [2][32][11]   : exp exchange  (double buf)

    const int bb  = threadIdx.x;               // 0..31 (lane)
    const int c   = threadIdx.y;               // 0..9  (warp id)
    const int tid = c * B_TILE + bb;
    const int i0  = blockIdx.x * I_TILE;
    const int b0  = blockIdx.y * B_TILE;
    const int b   = b0 + bb;

    // ---- Stage W tile transposed: global [ii][c][d][e] -> shared [c][ii][e][d]
    {
        const float4* Wg = (const float4*)(W + (size_t)i0 * NUM_CAPS * DIM_VEC * IN_DIM);
        #pragma unroll 4
        for (int k = tid; k < I_TILE * NUM_CAPS * DIM_VEC * 2; k += NTH) {
            float4 w4 = Wg[k];                       // coalesced LDG.128
            int eh = k & 1;
            int d  = (k >> 1) & 15;
            int cc = (k >> 5) % NUM_CAPS;
            int ii = k / (NUM_CAPS * DIM_VEC * 2);
            float* dst = ws + ((cc * I_TILE + ii) * IN_DIM) * DIM_VEC + d;
            int e0 = eh * 4;
            dst[(e0 + 0) * DIM_VEC] = w4.x;
            dst[(e0 + 1) * DIM_VEC] = w4.y;
            dst[(e0 + 2) * DIM_VEC] = w4.z;
            dst[(e0 + 3) * DIM_VEC] = w4.w;
        }
    }
    // ---- Stage x tile: xs[j][lb], coalesced global reads, conflict-free writes
    for (int t = tid; t < B_TILE * I_TILE * IN_DIM; t += NTH) {
        int lb = t >> 7;
        int j  = t & 127;
        xs[j * (B_TILE + 1) + lb] = x[(size_t)(b0 + lb) * (IN_CAPS * IN_DIM) + i0 * IN_DIM + j];
    }

    // ---- v = squash(s_prev) for this (b,c); invariant over i
    ull vv2[DIM_VEC / 2];
    if (PASS > 0) {
        const float* sp = g_sbuf[PASS - 1] + (b * NUM_CAPS + c) * DIM_VEC;
        float sv[DIM_VEC]; float sq = 0.f;
        #pragma unroll
        for (int d = 0; d < DIM_VEC; d++) { sv[d] = sp[d]; sq = fmaf(sv[d], sv[d], sq); }
        float scale = sq / (1.f + sq) * rsqrtf(sq + EPS);
        #pragma unroll
        for (int p = 0; p < 8; p++) vv2[p] = pack2(scale * sv[2 * p], scale * sv[2 * p + 1]);
    }
    __syncthreads();

    ull sacc2[8];
    #pragma unroll
    for (int p = 0; p < 8; p++) sacc2[p] = pack2(0.f, 0.f);

    #pragma unroll 1
    for (int ii = 0; ii < I_TILE; ii++) {
        const int i = i0 + ii;

        // x values packed (dup into both halves)
        ull x2[IN_DIM];
        #pragma unroll
        for (int e = 0; e < IN_DIM; e++) {
            float xv = xs[(ii * IN_DIM + e) * (B_TILE + 1) + bb];
            x2[e] = pack2(xv, xv);
        }

        // u_hat pairs: uh2[p] holds (uh[2p], uh[2p+1]); W reads are warp-uniform LDS.64
        const ull* wrow = (const ull*)(ws + ((c * I_TILE + ii) * IN_DIM) * DIM_VEC);
        ull uh2[8];
        #pragma unroll
        for (int p = 0; p < 8; p++) {
            ull a = pack2(0.f, 0.f);
            #pragma unroll
            for (int e = 0; e < IN_DIM; e++)
                a = ffma2(wrow[e * 8 + p], x2[e], a);
            uh2[p] = a;
        }

        const float bs = __ldg(&bias[i * NUM_CAPS + c]);   // warp-uniform
        float bnew;
        if (PASS == 0) {
            bnew = bs;
        } else {
            ull ag2 = pack2(0.f, 0.f);
            #pragma unroll
            for (int p = 0; p < 8; p++) ag2 = ffma2(uh2[p], vv2[p], ag2);
            float alo, ahi; unpack2(ag2, alo, ahi);
            float agr = alo + ahi;
            if (PASS == 1) {
                bnew = agr + 2.f * bs;
                g_blog[(i * NUM_CAPS + c) * BATCH + b] = bnew;   // coalesced over bb
            } else {
                bnew = agr + g_blog[(i * NUM_CAPS + c) * BATCH + b] + bs;
            }
        }

        // softmax over 10 c's: single exp per thread, double-buffered exchange
        const int pb = ii & 1;
        float* mxr = smx + (pb * B_TILE + bb) * (NUM_CAPS + 1);  // stride 11: conflict-free
        float* exr = sme + (pb * B_TILE + bb) * (NUM_CAPS + 1);
        mxr[c] = bnew;
        __syncthreads();
        float m = mxr[0];
        #pragma unroll
        for (int k = 1; k < NUM_CAPS; k++) m = fmaxf(m, mxr[k]);
        float ex = __expf(bnew - m);
        exr[c] = ex;
        __syncthreads();
        float den = 0.f;
        #pragma unroll
        for (int k = 0; k < NUM_CAPS; k++) den += exr[k];
        float coef = __fdividef(ex, den);
        ull cf2 = pack2(coef, coef);
        #pragma unroll
        for (int p = 0; p < 8; p++) sacc2[p] = ffma2(cf2, uh2[p], sacc2[p]);
    }

    // partial s[b,c,:] over this block's 16 i's -> 72 atomic adds per address total
    float* sp = g_sbuf[PASS] + (b * NUM_CAPS + c) * DIM_VEC;
    #pragma unroll
    for (int p = 0; p < 8; p++) {
        float lo, hi; unpack2(sacc2[p], lo, hi);
        atomicAdd(&sp[2 * p], lo);
        atomicAdd(&sp[2 * p + 1], hi);
    }
}

// Final: out = squash(s2); re-zero all scratch for graph-replay determinism
__global__ void final_kernel(float* __restrict__ out)
{
    int t = blockIdx.x * blockDim.x + threadIdx.x;       // (b,c) row, 2560 total
    if (t < BATCH * NUM_CAPS) {
        float* sp = g_sbuf[2] + t * DIM_VEC;
        float sv[DIM_VEC]; float sq = 0.f;
        #pragma unroll
        for (int d = 0; d < DIM_VEC; d++) { sv[d] = sp[d]; sq = fmaf(sv[d], sv[d], sq); }
        float scale = sq / (1.f + sq) * rsqrtf(sq + EPS);
        float* dst = out + t * DIM_VEC;
        #pragma unroll
        for (int d = 0; d < DIM_VEC; d++) { dst[d] = scale * sv[d]; sp[d] = 0.f; }
        // zero s0, s1 (nobody reads them in this kernel)
        float* s0 = g_sbuf[0] + t * DIM_VEC;
        float* s1 = g_sbuf[1] + t * DIM_VEC;
        #pragma unroll
        for (int d = 0; d < DIM_VEC; d++) { s0[d] = 0.f; s1[d] = 0.f; }
    }
}

extern "C" void kernel_launch(void* const* d_in, const int* in_sizes, int n_in,
                              void* d_out, int out_size)
{
    const float* x = nullptr; const float* W = nullptr; const float* bias = nullptr;
    for (int k = 0; k < n_in; k++) {
        if (in_sizes[k] == BATCH * IN_CAPS * IN_DIM)                    x    = (const float*)d_in[k];
        else if (in_sizes[k] == IN_CAPS * NUM_CAPS * DIM_VEC * IN_DIM)  W    = (const float*)d_in[k];
        else if (in_sizes[k] == IN_CAPS * NUM_CAPS)                     bias = (const float*)d_in[k];
    }
    float* out = (float*)d_out;

    static bool attr_set = false;
    if (!attr_set) {
        cudaFuncSetAttribute(pass_kernel<0>, cudaFuncAttributeMaxDynamicSharedMemorySize, SMEM_BYTES);
        cudaFuncSetAttribute(pass_kernel<1>, cudaFuncAttributeMaxDynamicSharedMemorySize, SMEM_BYTES);
        cudaFuncSetAttribute(pass_kernel<2>, cudaFuncAttributeMaxDynamicSharedMemorySize, SMEM_BYTES);
        attr_set = true;
    }

    dim3 blk(B_TILE, NUM_CAPS);
    dim3 grd(N_ITILES, N_BTILES);

    pass_kernel<0><<<grd, blk, SMEM_BYTES>>>(x, W, bias);
    pass_kernel<1><<<grd, blk, SMEM_BYTES>>>(x, W, bias);
    pass_kernel<2><<<grd, blk, SMEM_BYTES>>>(x, W, bias);
    final_kernel<<<(BATCH * NUM_CAPS + 127) / 128, 128>>>(out);
}